// round 1
// baseline (speedup 1.0000x reference)
#include <cuda_runtime.h>
#include <math.h>
#include <math_constants.h>

#define H 128
#define NSEG 129
#define THRESH 0.045f
#define INV_TAU 0.05f
#define MAXB 512
#define MAXN (1<<21)

// -------- scratch (no cudaMalloc allowed) --------
__device__ float  g_bp[H];               // sorted layer-1 breakpoints
__device__ float2 g_tab[NSEG * H];       // per-segment (alpha, beta) per unit j
__device__ int    g_blockLast[MAXB];
__device__ int    g_blockCnt[MAXB];
__device__ int    g_seed[MAXB];
__device__ int    g_lastIdx[MAXN];

// -------- P0: breakpoints + bitonic sort (1 block, 128 threads) --------
__global__ void k_sortbp(const float* __restrict__ W1, const float* __restrict__ B1) {
    __shared__ float s[H];
    int t = threadIdx.x;
    float w = W1[t], b = B1[t];
    s[t] = (w == 0.0f) ? CUDART_INF_F : (-b / w);
    __syncthreads();
    for (int k = 2; k <= H; k <<= 1) {
        for (int j = k >> 1; j > 0; j >>= 1) {
            int ixj = t ^ j;
            if (ixj > t) {
                bool up = ((t & k) == 0);
                float a = s[t], c = s[ixj];
                if (up ? (a > c) : (a < c)) { s[t] = c; s[ixj] = a; }
            }
            __syncthreads();
        }
    }
    g_bp[t] = s[t];
}

// -------- P1: per-segment alpha/beta table (129 blocks, 128 threads) --------
__global__ void k_table(const float* __restrict__ W1, const float* __restrict__ B1,
                        const float* __restrict__ W2, const float* __restrict__ B2) {
    int s = blockIdx.x, j = threadIdx.x;
    __shared__ float sw[H], sb[H];
    sw[j] = W1[j]; sb[j] = B1[j];
    __syncthreads();
    float L = (s == 0)        ? -CUDART_INF_F : g_bp[s - 1];
    float R = (s == NSEG - 1) ?  CUDART_INF_F : g_bp[s];
    float a = 0.0f, be = B2[j];
    const float* w2row = W2 + j * H;
    #pragma unroll 4
    for (int m = 0; m < H; m++) {
        float w = sw[m], b = sb[m];
        bool act;
        if (w > 0.0f)      act = ((-b / w) <= L);   // active for x > t_m
        else if (w < 0.0f) act = ((-b / w) >= R);   // active for x < t_m
        else               act = (b > 0.0f);        // constant unit
        if (act) {
            float c = w2row[m];
            a  = fmaf(c, w, a);
            be = fmaf(c, b, be);
        }
    }
    g_tab[s * H + j] = make_float2(a, be);
}

__device__ __forceinline__ bool maskf(const float* x, long i) {
    if (i == 0) return true;
    return fabsf(x[i] - x[i - 1]) > THRESH;
}

// -------- P2: per-block last-active + count --------
__global__ void k_pass1(const float* __restrict__ x, int N, int IT) {
    int b = blockIdx.x, t = threadIdx.x;
    long base = ((long)b * blockDim.x + t) * (long)IT;
    int loc = -1, cnt = 0;
    for (int i = 0; i < IT; i++) {
        long idx = base + i;
        if (idx < N && maskf(x, idx)) { loc = (int)idx; cnt++; }
    }
    __shared__ int sL[256], sC[256];
    sL[t] = loc; sC[t] = cnt;
    __syncthreads();
    for (int s = 128; s > 0; s >>= 1) {
        if (t < s) { sL[t] = max(sL[t], sL[t + s]); sC[t] += sC[t + s]; }
        __syncthreads();
    }
    if (t == 0) { g_blockLast[b] = sL[0]; g_blockCnt[b] = sC[0]; }
}

// -------- P3: single-block exclusive cummax over blocks + n_active --------
__global__ void k_pass2(int nB, float* __restrict__ out, int out_size, int N) {
    __shared__ int s[MAXB];
    __shared__ int sc[MAXB];
    int t = threadIdx.x;  // blockDim == 512 == MAXB
    int v = (t < nB) ? g_blockLast[t] : -1;
    int c = (t < nB) ? g_blockCnt[t]  : 0;
    s[t] = v;
    __syncthreads();
    int incl = v;
    for (int o = 1; o < MAXB; o <<= 1) {
        int u = (t >= o) ? s[t - o] : -1;
        __syncthreads();
        incl = max(incl, u);
        s[t] = incl;
        __syncthreads();
    }
    int excl = (t == 0) ? -1 : s[t - 1];
    if (t < nB) g_seed[t] = excl;
    sc[t] = c;
    __syncthreads();
    for (int st = MAXB / 2; st > 0; st >>= 1) {
        if (t < st) sc[t] += sc[t + st];
        __syncthreads();
    }
    if (t == 0 && out_size > N) out[N] = (float)sc[0];
    for (int i = N + 1 + t; i < out_size; i += blockDim.x) out[i] = 0.0f;
}

// -------- P4: per-row last-active index (block-seeded cummax scan) --------
__global__ void k_pass3a(const float* __restrict__ x, int N, int IT) {
    int b = blockIdx.x, t = threadIdx.x;
    long base = ((long)b * blockDim.x + t) * (long)IT;
    int lane = t & 31, w = t >> 5;
    int loc = -1;
    for (int i = 0; i < IT; i++) {
        long idx = base + i;
        if (idx < N && maskf(x, idx)) loc = (int)idx;
    }
    // warp inclusive cummax
    int v = loc;
    #pragma unroll
    for (int o = 1; o < 32; o <<= 1) {
        int u = __shfl_up_sync(0xffffffffu, v, o);
        if (lane >= o) v = max(v, u);
    }
    int excl = __shfl_up_sync(0xffffffffu, v, 1);
    if (lane == 0) excl = -1;
    __shared__ int wtot[8], wexc[8];
    if (lane == 31) wtot[w] = v;
    __syncthreads();
    if (t == 0) {
        int run = -1;
        for (int i = 0; i < (int)(blockDim.x >> 5); i++) { wexc[i] = run; run = max(run, wtot[i]); }
    }
    __syncthreads();
    int run = max(g_seed[b], max(wexc[w], excl));
    for (int i = 0; i < IT; i++) {
        long idx = base + i;
        if (idx < N) {
            if (maskf(x, idx)) run = (int)idx;
            g_lastIdx[idx] = run;
        }
    }
}

// -------- P5: warp-per-row evaluator --------
__global__ void k_pass3b(const float* __restrict__ x, const float* __restrict__ W3,
                         const float* __restrict__ B3, float* __restrict__ out, int N) {
    __shared__ float sbp[H];
    int t = threadIdx.x;
    if (t < H) sbp[t] = g_bp[t];
    __syncthreads();
    int lane = t & 31;
    float w3r0 = __ldg(&W3[lane]);
    float w3r1 = __ldg(&W3[lane + 32]);
    float w3r2 = __ldg(&W3[lane + 64]);
    float w3r3 = __ldg(&W3[lane + 96]);
    float b3v  = __ldg(&B3[0]);
    int gw  = (gridDim.x * blockDim.x) >> 5;
    int wid = (blockIdx.x * blockDim.x + t) >> 5;
    for (int r = wid; r < N; r += gw) {
        int last = g_lastIdx[r];
        float xv = __ldg(&x[last]);
        // seg = count of breakpoints < xv  (all lanes redundant; smem broadcast)
        int seg = 0;
        #pragma unroll
        for (int st = 64; st > 0; st >>= 1) {
            int c = seg + st;
            if (c <= H && sbp[c - 1] < xv) seg = c;
        }
        const float2* tab = g_tab + seg * H;
        float2 ab;
        ab = __ldg(&tab[lane]);
        float acc = w3r0 * fmaxf(fmaf(ab.x, xv, ab.y), 0.0f);
        ab = __ldg(&tab[lane + 32]);
        acc = fmaf(w3r1, fmaxf(fmaf(ab.x, xv, ab.y), 0.0f), acc);
        ab = __ldg(&tab[lane + 64]);
        acc = fmaf(w3r2, fmaxf(fmaf(ab.x, xv, ab.y), 0.0f), acc);
        ab = __ldg(&tab[lane + 96]);
        acc = fmaf(w3r3, fmaxf(fmaf(ab.x, xv, ab.y), 0.0f), acc);
        #pragma unroll
        for (int o = 16; o > 0; o >>= 1) acc += __shfl_xor_sync(0xffffffffu, acc, o);
        if (lane == 0)
            out[r] = (acc + b3v) * __expf((float)(last - r) * INV_TAU);
    }
}

extern "C" void kernel_launch(void* const* d_in, const int* in_sizes, int n_in,
                              void* d_out, int out_size) {
    const float* x  = (const float*)d_in[0];
    const float* W1 = (const float*)d_in[1];
    const float* b1 = (const float*)d_in[2];
    const float* W2 = (const float*)d_in[3];
    const float* b2 = (const float*)d_in[4];
    const float* W3 = (const float*)d_in[5];
    const float* b3 = (const float*)d_in[6];
    float* out = (float*)d_out;
    int N = in_sizes[0];

    // setup: breakpoints + segment table
    k_sortbp<<<1, H>>>(W1, b1);
    k_table<<<NSEG, H>>>(W1, b1, W2, b2);

    // scan geometry: <= MAXB blocks of 256 threads, IT rows/thread
    const int thr = 256;
    long total = N;
    int IT = (int)((total + (long)MAXB * thr - 1) / ((long)MAXB * thr));
    if (IT < 1) IT = 1;
    int grid1 = (int)((total + (long)thr * IT - 1) / ((long)thr * IT));

    k_pass1<<<grid1, thr>>>(x, N, IT);
    k_pass2<<<1, MAXB>>>(grid1, out, out_size, N);
    k_pass3a<<<grid1, thr>>>(x, N, IT);
    k_pass3b<<<1184, 256>>>(x, W3, b3, out, N);
}

// round 2
// speedup vs baseline: 2.4127x; 2.4127x over previous
#include <cuda_runtime.h>
#include <math.h>
#include <math_constants.h>

#define H 128
#define NSEG 129
#define NPIECE 129
#define THRESH 0.045f
#define INV_TAU 0.05f
#define MAXB 512
#define GRID 148
#define THR 1024

// -------- scratch (no cudaMalloc allowed) --------
__device__ float  g_bp[H];                  // sorted layer-1 breakpoints
__device__ float  g_cut[NSEG * H];          // sorted layer-2 cuts per segment (+INF pad)
__device__ float2 g_AB[NSEG * NPIECE];      // piecewise (A, B) incl. b3, w3 folded in
__device__ int    g_blockLast[MAXB];
__device__ int    g_blockCnt[MAXB];
__device__ int    g_seed[MAXB];

// -------- P0: layer-1 breakpoints + bitonic sort (1 block, 128 thr) --------
__global__ void k_sortbp(const float* __restrict__ W1, const float* __restrict__ B1) {
    __shared__ float s[H];
    int t = threadIdx.x;
    float w = W1[t], b = B1[t];
    s[t] = (w == 0.0f) ? CUDART_INF_F : (-b / w);
    __syncthreads();
    for (int k = 2; k <= H; k <<= 1)
        for (int j = k >> 1; j > 0; j >>= 1) {
            int ixj = t ^ j;
            if (ixj > t) {
                bool up = ((t & k) == 0);
                float a = s[t], c = s[ixj];
                if (up ? (a > c) : (a < c)) { s[t] = c; s[ixj] = a; }
            }
            __syncthreads();
        }
    g_bp[t] = s[t];
}

// -------- P1: per-segment collapsed piecewise-linear table (129 blocks) ----
__global__ void k_build(const float* __restrict__ W1, const float* __restrict__ B1,
                        const float* __restrict__ W2, const float* __restrict__ B2,
                        const float* __restrict__ W3, const float* __restrict__ B3) {
    int s = blockIdx.x, j = threadIdx.x;
    __shared__ float sw[H], sb[H];
    __shared__ float skey[H], sdA[H], sdB[H];
    __shared__ float rA[H], rB[H];
    sw[j] = W1[j]; sb[j] = B1[j];
    __syncthreads();
    float L = (s == 0)        ? -CUDART_INF_F : g_bp[s - 1];
    float R = (s == NSEG - 1) ?  CUDART_INF_F : g_bp[s];
    // composite layer-2 pre-activation within segment: a2_j = a*x + be
    float a = 0.0f, be = B2[j];
    const float* w2row = W2 + j * H;
    #pragma unroll 4
    for (int m = 0; m < H; m++) {
        float w = sw[m], b = sb[m];
        bool act;
        if (w > 0.0f)      act = ((-b / w) <= L);
        else if (w < 0.0f) act = ((-b / w) >= R);
        else               act = (b > 0.0f);
        if (act) { float c = w2row[m]; a = fmaf(c, w, a); be = fmaf(c, b, be); }
    }
    float w3 = W3[j];
    // layer-2 relu cut for unit j inside this segment
    float c = -be / a;
    bool hasbp = (a != 0.0f) && (c > L) && (c < R);
    // active at left edge of segment?
    bool actL;
    if (a > 0.0f)      actL = (c <= L);
    else if (a < 0.0f) actL = (c > L);
    else               actL = (be > 0.0f);
    rA[j] = actL ? w3 * a  : 0.0f;
    rB[j] = actL ? w3 * be : 0.0f;
    float sgn = (a > 0.0f) ? 1.0f : -1.0f;   // crossing turns unit on (+) or off (-)
    skey[j] = hasbp ? c : CUDART_INF_F;
    sdA[j]  = hasbp ? sgn * w3 * a  : 0.0f;
    sdB[j]  = hasbp ? sgn * w3 * be : 0.0f;
    __syncthreads();
    // reduce left-edge coefficients
    for (int st = 64; st > 0; st >>= 1) {
        if (j < st) { rA[j] += rA[j + st]; rB[j] += rB[j + st]; }
        __syncthreads();
    }
    float A0 = rA[0], B0 = rB[0] + B3[0];
    // bitonic sort cuts (with delta payloads) ascending
    for (int k = 2; k <= H; k <<= 1)
        for (int jj = k >> 1; jj > 0; jj >>= 1) {
            int ixj = j ^ jj;
            if (ixj > j) {
                bool up = ((j & k) == 0);
                float ka = skey[j], kb = skey[ixj];
                if (up ? (ka > kb) : (ka < kb)) {
                    skey[j] = kb; skey[ixj] = ka;
                    float t1 = sdA[j]; sdA[j] = sdA[ixj]; sdA[ixj] = t1;
                    float t2 = sdB[j]; sdB[j] = sdB[ixj]; sdB[ixj] = t2;
                }
            }
            __syncthreads();
        }
    // inclusive scan of deltas over sorted cuts (Hillis-Steele)
    for (int off = 1; off < H; off <<= 1) {
        float va = sdA[j], vb = sdB[j];
        float ua = (j >= off) ? sdA[j - off] : 0.0f;
        float ub = (j >= off) ? sdB[j - off] : 0.0f;
        __syncthreads();
        sdA[j] = va + ua; sdB[j] = vb + ub;
        __syncthreads();
    }
    g_cut[s * H + j] = skey[j];
    if (j == 0) g_AB[s * NPIECE] = make_float2(A0, B0);
    g_AB[s * NPIECE + 1 + j] = make_float2(A0 + sdA[j], B0 + sdB[j]);
}

// -------- P2: per-block last-active + count --------
__global__ void k_pass1(const float* __restrict__ x, int N, int IT) {
    int b = blockIdx.x, t = threadIdx.x;
    long base = ((long)b * THR + t) * (long)IT;
    float prev = 0.0f;
    if (base > 0 && base < N) prev = x[base - 1];
    int loc = -1, cnt = 0;
    for (int i = 0; i < IT; i++) {
        long idx = base + i;
        if (idx < N) {
            float cur = x[idx];
            bool m = (idx == 0) || (fabsf(cur - prev) > THRESH);
            prev = cur;
            if (m) { loc = (int)idx; cnt++; }
        }
    }
    __shared__ int sL[THR], sC[THR];
    sL[t] = loc; sC[t] = cnt;
    __syncthreads();
    for (int s = THR / 2; s > 0; s >>= 1) {
        if (t < s) { sL[t] = max(sL[t], sL[t + s]); sC[t] += sC[t + s]; }
        __syncthreads();
    }
    if (t == 0) { g_blockLast[b] = sL[0]; g_blockCnt[b] = sC[0]; }
}

// -------- P3: exclusive cummax over blocks + n_active --------
__global__ void k_pass2(int nB, float* __restrict__ out, int out_size, int N) {
    __shared__ int s[MAXB];
    __shared__ int sc[MAXB];
    int t = threadIdx.x;  // blockDim == MAXB
    int v = (t < nB) ? g_blockLast[t] : -1;
    int c = (t < nB) ? g_blockCnt[t]  : 0;
    s[t] = v;
    __syncthreads();
    int incl = v;
    for (int o = 1; o < MAXB; o <<= 1) {
        int u = (t >= o) ? s[t - o] : -1;
        __syncthreads();
        incl = max(incl, u);
        s[t] = incl;
        __syncthreads();
    }
    int excl = (t == 0) ? -1 : s[t - 1];
    if (t < nB) g_seed[t] = excl;
    sc[t] = c;
    __syncthreads();
    for (int st = MAXB / 2; st > 0; st >>= 1) {
        if (t < st) sc[t] += sc[t + st];
        __syncthreads();
    }
    if (t == 0 && out_size > N) out[N] = (float)sc[0];
    for (int i = N + 1 + t; i < out_size; i += MAXB) out[i] = 0.0f;
}

// -------- P4: fused last-idx scan + piecewise-linear eval --------
__global__ void __launch_bounds__(THR, 1)
k_fused(const float* __restrict__ x, float* __restrict__ out, int N, int IT) {
    extern __shared__ char smem[];
    float2* sAB  = (float2*)smem;                   // NSEG*NPIECE
    float*  scut = (float*)(sAB + NSEG * NPIECE);   // NSEG*H
    float*  sbp  = scut + NSEG * H;                 // H
    int t = threadIdx.x, b = blockIdx.x;
    // cooperative table load into smem
    {
        const float4* src = (const float4*)g_AB;    // 133128 B / 16 = 8320.5 -> do float2 tail-safe
        float4* dst = (float4*)sAB;
        int n4 = (NSEG * NPIECE * 2) / 4;           // 8320 float4s cover 16640 float2... see below
        for (int i = t; i < n4; i += THR) dst[i] = src[i];
        // last float2 (NSEG*NPIECE = 16641 is odd)
        if (t == 0) sAB[NSEG * NPIECE - 1] = g_AB[NSEG * NPIECE - 1];
        for (int i = t; i < NSEG * H; i += THR) scut[i] = g_cut[i];
        if (t < H) sbp[t] = g_bp[t];
    }
    // local event scan
    long base = ((long)b * THR + t) * (long)IT;
    float prev0 = 0.0f;
    if (base > 0 && base < N) prev0 = __ldg(&x[base - 1]);
    float prev = prev0;
    int loc = -1;
    for (int i = 0; i < IT; i++) {
        long idx = base + i;
        if (idx < N) {
            float cur = __ldg(&x[idx]);
            bool m = (idx == 0) || (fabsf(cur - prev) > THRESH);
            prev = cur;
            if (m) loc = (int)idx;
        }
    }
    // warp inclusive cummax -> block exclusive prefix
    int lane = t & 31, w = t >> 5;
    int v = loc;
    #pragma unroll
    for (int o = 1; o < 32; o <<= 1) {
        int u = __shfl_up_sync(0xffffffffu, v, o);
        if (lane >= o) v = max(v, u);
    }
    int excl = __shfl_up_sync(0xffffffffu, v, 1);
    if (lane == 0) excl = -1;
    __shared__ int wtot[THR / 32], wexc[THR / 32];
    if (lane == 31) wtot[w] = v;
    __syncthreads();
    if (t == 0) {
        int run = -1;
        #pragma unroll
        for (int i = 0; i < THR / 32; i++) { wexc[i] = run; run = max(run, wtot[i]); }
    }
    __syncthreads();
    int run = max(g_seed[b], max(wexc[w], excl));
    // eval loop
    prev = prev0;
    for (int i = 0; i < IT; i++) {
        long idx = base + i;
        if (idx >= N) break;
        float cur = __ldg(&x[idx]);
        bool m = (idx == 0) || (fabsf(cur - prev) > THRESH);
        prev = cur;
        if (m) run = (int)idx;
        float xv = (run == (int)idx) ? cur : __ldg(&x[run]);
        // segment = count of bp < xv
        int seg = 0;
        #pragma unroll
        for (int st = 64; st; st >>= 1) {
            int cnd = seg + st;
            if (cnd <= H && sbp[cnd - 1] < xv) seg = cnd;
        }
        // piece = count of cuts < xv within segment
        const float* cut = scut + seg * H;
        int p = 0;
        #pragma unroll
        for (int st = 64; st; st >>= 1) {
            int cnd = p + st;
            if (cnd <= H && cut[cnd - 1] < xv) p = cnd;
        }
        float2 ab = sAB[seg * NPIECE + p];
        float y = fmaf(ab.x, xv, ab.y);
        out[idx] = y * __expf((float)(run - (int)idx) * INV_TAU);
    }
}

extern "C" void kernel_launch(void* const* d_in, const int* in_sizes, int n_in,
                              void* d_out, int out_size) {
    const float* x  = (const float*)d_in[0];
    const float* W1 = (const float*)d_in[1];
    const float* b1 = (const float*)d_in[2];
    const float* W2 = (const float*)d_in[3];
    const float* b2 = (const float*)d_in[4];
    const float* W3 = (const float*)d_in[5];
    const float* b3 = (const float*)d_in[6];
    float* out = (float*)d_out;
    int N = in_sizes[0];

    k_sortbp<<<1, H>>>(W1, b1);
    k_build<<<NSEG, H>>>(W1, b1, W2, b2, W3, b3);

    long total = N;
    int IT = (int)((total + (long)GRID * THR - 1) / ((long)GRID * THR));
    if (IT < 1) IT = 1;
    int grid1 = (int)((total + (long)THR * IT - 1) / ((long)THR * IT));  // <= GRID <= MAXB

    size_t smem = (size_t)(NSEG * NPIECE) * sizeof(float2)
                + (size_t)(NSEG * H) * sizeof(float)
                + (size_t)H * sizeof(float);
    cudaFuncSetAttribute(k_fused, cudaFuncAttributeMaxDynamicSharedMemorySize, (int)smem);

    k_pass1<<<grid1, THR>>>(x, N, IT);
    k_pass2<<<1, MAXB>>>(grid1, out, out_size, N);
    k_fused<<<grid1, THR, smem>>>(x, out, N, IT);
}

// round 3
// speedup vs baseline: 3.2326x; 1.3398x over previous
#include <cuda_runtime.h>
#include <math.h>
#include <math_constants.h>

#define H 128
#define NSEG 129
#define NPIECE 129
#define THRESH 0.045f
#define INV_TAU 0.05f
#define THR 1024
#define NWARP (THR / 32)
#define GRIDMAX 152
#define NCMAX (NSEG * H + (NSEG - 1))   // 16640 max global cuts
#define NPMAX (NCMAX + 1)               // 16641 max pieces
#define NB 8192
#define XLO (-8.0f)
#define BINSCALE 512.0f                 // NB / 16

// -------- scratch (no cudaMalloc allowed) --------
__device__ float  g_bp[H];
__device__ float  g_cut[NSEG * H];                 // per-seg sorted cuts (INF pad)
__device__ float2 g_AB[NSEG * NPIECE];             // per-seg pieces
__device__ int    g_cnt[NSEG];                     // finite cuts per segment
__device__ __align__(16) float  g_cutC[NCMAX];     // global merged cuts
__device__ __align__(16) float2 g_ABC[NPMAX];      // global merged pieces
__device__ unsigned short g_bin[NB + 1];           // bin -> first piece
__device__ int    g_meta[4];                       // [0] = NC
__device__ unsigned long long g_sync[GRIDMAX];     // lookback slots

// -------- P0: layer-1 breakpoints + bitonic sort --------
__global__ void k_sortbp(const float* __restrict__ W1, const float* __restrict__ B1) {
    __shared__ float s[H];
    int t = threadIdx.x;
    float w = W1[t], b = B1[t];
    s[t] = (w == 0.0f) ? CUDART_INF_F : (-b / w);
    __syncthreads();
    for (int k = 2; k <= H; k <<= 1)
        for (int j = k >> 1; j > 0; j >>= 1) {
            int ixj = t ^ j;
            if (ixj > t) {
                bool up = ((t & k) == 0);
                float a = s[t], c = s[ixj];
                if (up ? (a > c) : (a < c)) { s[t] = c; s[ixj] = a; }
            }
            __syncthreads();
        }
    g_bp[t] = s[t];
}

// -------- P1: per-segment collapsed piecewise table + cut count --------
__global__ void k_build(const float* __restrict__ W1, const float* __restrict__ B1,
                        const float* __restrict__ W2, const float* __restrict__ B2,
                        const float* __restrict__ W3, const float* __restrict__ B3) {
    int s = blockIdx.x, j = threadIdx.x;
    int lane = j & 31, w = j >> 5;
    __shared__ float sw[H], sb[H];
    __shared__ float skey[H], sdA[H], sdB[H];
    __shared__ float rA[H], rB[H];
    __shared__ int scw[4];
    sw[j] = W1[j]; sb[j] = B1[j];
    __syncthreads();
    float L = (s == 0)        ? -CUDART_INF_F : g_bp[s - 1];
    float R = (s == NSEG - 1) ?  CUDART_INF_F : g_bp[s];
    float a = 0.0f, be = B2[j];
    const float* w2row = W2 + j * H;
    #pragma unroll 4
    for (int m = 0; m < H; m++) {
        float ww = sw[m], bb = sb[m];
        bool act;
        if (ww > 0.0f)      act = ((-bb / ww) <= L);
        else if (ww < 0.0f) act = ((-bb / ww) >= R);
        else                act = (bb > 0.0f);
        if (act) { float c = w2row[m]; a = fmaf(c, ww, a); be = fmaf(c, bb, be); }
    }
    float w3 = W3[j];
    float c = -be / a;
    bool hasbp = (a != 0.0f) && (c > L) && (c < R);
    bool actL;
    if (a > 0.0f)      actL = (c <= L);
    else if (a < 0.0f) actL = (c > L);
    else               actL = (be > 0.0f);
    rA[j] = actL ? w3 * a  : 0.0f;
    rB[j] = actL ? w3 * be : 0.0f;
    float sgn = (a > 0.0f) ? 1.0f : -1.0f;
    skey[j] = hasbp ? c : CUDART_INF_F;
    sdA[j]  = hasbp ? sgn * w3 * a  : 0.0f;
    sdB[j]  = hasbp ? sgn * w3 * be : 0.0f;
    // cut count
    unsigned bal = __ballot_sync(0xffffffffu, hasbp);
    if (lane == 0) scw[w] = __popc(bal);
    __syncthreads();
    if (j == 0) g_cnt[s] = scw[0] + scw[1] + scw[2] + scw[3];
    // reduce left-edge coefficients
    for (int st = 64; st > 0; st >>= 1) {
        if (j < st) { rA[j] += rA[j + st]; rB[j] += rB[j + st]; }
        __syncthreads();
    }
    float A0 = rA[0], B0 = rB[0] + B3[0];
    // bitonic sort cuts with payloads
    for (int k = 2; k <= H; k <<= 1)
        for (int jj = k >> 1; jj > 0; jj >>= 1) {
            int ixj = j ^ jj;
            if (ixj > j) {
                bool up = ((j & k) == 0);
                float ka = skey[j], kb = skey[ixj];
                if (up ? (ka > kb) : (ka < kb)) {
                    skey[j] = kb; skey[ixj] = ka;
                    float t1 = sdA[j]; sdA[j] = sdA[ixj]; sdA[ixj] = t1;
                    float t2 = sdB[j]; sdB[j] = sdB[ixj]; sdB[ixj] = t2;
                }
            }
            __syncthreads();
        }
    // inclusive scan of deltas
    for (int off = 1; off < H; off <<= 1) {
        float va = sdA[j], vb = sdB[j];
        float ua = (j >= off) ? sdA[j - off] : 0.0f;
        float ub = (j >= off) ? sdB[j - off] : 0.0f;
        __syncthreads();
        sdA[j] = va + ua; sdB[j] = vb + ub;
        __syncthreads();
    }
    g_cut[s * H + j] = skey[j];
    if (j == 0) g_AB[s * NPIECE] = make_float2(A0, B0);
    g_AB[s * NPIECE + 1 + j] = make_float2(A0 + sdA[j], B0 + sdB[j]);
}

// -------- P2: compact per-segment tables into one global sorted table -----
__global__ void k_compact() {
    int s = blockIdx.x, t = threadIdx.x;
    __shared__ int soff;
    if (t == 0) {
        int o = 0;
        for (int u = 0; u < s; u++) o += g_cnt[u] + 1;
        soff = o;
    }
    __syncthreads();
    int off = soff;
    int cnt = g_cnt[s];
    for (int k = t; k < cnt; k += H) g_cutC[off + k] = g_cut[s * H + k];
    if (t == 0 && s < NSEG - 1) g_cutC[off + cnt] = g_bp[s];
    for (int k = t; k <= cnt; k += H) g_ABC[off + k] = g_AB[s * NPIECE + k];
    if (t == 0 && s == NSEG - 1) g_meta[0] = off + cnt;   // NC (no trailing bp)
}

// -------- P3: bin index + zero the lookback slots --------
__global__ void k_bins() {
    int i = blockIdx.x * blockDim.x + threadIdx.x;
    if (i < GRIDMAX) g_sync[i] = 0ull;
    if (i > NB) return;
    int NC = g_meta[0];
    float edge = XLO + (float)i * (1.0f / BINSCALE);
    int lo = 0, hi = NC;
    while (lo < hi) {
        int mid = (lo + hi) >> 1;
        if (g_cutC[mid] < edge) lo = mid + 1; else hi = mid;
    }
    g_bin[i] = (unsigned short)lo;
}

// -------- P4: fully fused scan + lookback + eval --------
template <int IT>
__global__ void __launch_bounds__(THR, 1)
k_main(const float* __restrict__ x, float* __restrict__ out, int N, int out_size) {
    extern __shared__ char smem[];
    float*  scut = (float*)smem;                                   // NCMAX floats
    float2* sAB  = (float2*)(smem + NCMAX * sizeof(float));        // NPMAX float2
    unsigned short* sbin =
        (unsigned short*)(smem + NCMAX * sizeof(float) + NPMAX * sizeof(float2));
    __shared__ int swarp[NWARP];
    __shared__ unsigned ssum[NWARP];
    __shared__ int sSeedSh;
    __shared__ int sCntOwn;

    int t = threadIdx.x, b = blockIdx.x;
    int lane = t & 31, w = t >> 5;
    long blockBase = (long)b * THR * IT;

    float xr[IT];
    int   rr[IT];
    int carry = -1, cntLoc = 0;

    // ---- phase A: coalesced event scan, tile-cyclic ----
    #pragma unroll
    for (int tile = 0; tile < IT; tile++) {
        long row = blockBase + (long)tile * THR + t;
        bool valid = row < N;
        float cur = 0.0f, pv = 0.0f;
        if (valid) {
            cur = __ldg(x + row);
            pv = (row > 0) ? __ldg(x + row - 1) : cur;
        }
        bool m = valid && ((row == 0) || fabsf(cur - pv) > THRESH);
        cntLoc += m ? 1 : 0;
        int v = m ? (int)row : -1;
        #pragma unroll
        for (int o = 1; o < 32; o <<= 1) {
            int u = __shfl_up_sync(0xffffffffu, v, o);
            if (lane >= o) v = max(v, u);
        }
        if (lane == 31) swarp[w] = v;
        __syncthreads();
        if (w == 0) {
            int z = swarp[lane];
            #pragma unroll
            for (int o = 1; o < 32; o <<= 1) {
                int u = __shfl_up_sync(0xffffffffu, z, o);
                if (lane >= o) z = max(z, u);
            }
            swarp[lane] = z;
        }
        __syncthreads();
        int pre = (w > 0) ? swarp[w - 1] : -1;
        v = max(v, max(pre, carry));
        rr[tile] = v;
        xr[tile] = cur;
        carry = max(carry, swarp[NWARP - 1]);
        __syncthreads();
    }

    // ---- count reduce + publish ----
    {
        int c = cntLoc;
        #pragma unroll
        for (int o = 16; o; o >>= 1) c += __shfl_xor_sync(0xffffffffu, c, o);
        if (lane == 0) swarp[w] = c;
        __syncthreads();
        if (t == 0) {
            int s = 0;
            #pragma unroll
            for (int i = 0; i < NWARP; i++) s += swarp[i];
            sCntOwn = s;
            unsigned long long pack =
                ((unsigned long long)(unsigned)(carry + 2) << 32) | (unsigned)s;
            atomicExch(&g_sync[b], pack);
        }
        __syncthreads();
    }

    // ---- decoupled lookback (all CTAs co-resident; grid <= GRIDMAX) ----
    {
        int lastMax = -1;
        unsigned sumU = 0;
        for (int i = t; i < b; i += THR) {
            volatile unsigned long long* p = (volatile unsigned long long*)(g_sync + i);
            unsigned long long v;
            do { v = *p; } while (v == 0ull);
            lastMax = max(lastMax, (int)(unsigned)(v >> 32) - 2);
            sumU += (unsigned)(v & 0xffffffffull);
        }
        #pragma unroll
        for (int o = 16; o; o >>= 1) {
            lastMax = max(lastMax, __shfl_xor_sync(0xffffffffu, lastMax, o));
            sumU += __shfl_xor_sync(0xffffffffu, sumU, o);
        }
        if (lane == 0) { swarp[w] = lastMax; ssum[w] = sumU; }
        __syncthreads();
        if (t == 0) {
            int mx = -1; unsigned s2 = 0;
            #pragma unroll
            for (int i = 0; i < NWARP; i++) { mx = max(mx, swarp[i]); s2 += ssum[i]; }
            sSeedSh = mx;
            if (b == gridDim.x - 1 && out_size > N)
                out[N] = (float)(s2 + (unsigned)sCntOwn);
        }
        if (b == 0)
            for (int i = N + 1 + t; i < out_size; i += THR) out[i] = 0.0f;
        __syncthreads();
    }
    int seed = sSeedSh;

    // ---- load global piecewise table into smem ----
    {
        int NC = g_meta[0];
        int NP = NC + 1;
        const float4* c4 = (const float4*)g_cutC;
        float4* e4 = (float4*)scut;
        int m4 = NC >> 2;
        for (int i = t; i < m4; i += THR) e4[i] = c4[i];
        for (int i = (m4 << 2) + t; i < NC; i += THR) scut[i] = g_cutC[i];
        const float4* s4 = (const float4*)g_ABC;
        float4* d4 = (float4*)sAB;
        int n4 = (NP * 2) >> 2;
        for (int i = t; i < n4; i += THR) d4[i] = s4[i];
        for (int i = (n4 << 2) + t; i < NP * 2; i += THR)
            ((float*)sAB)[i] = ((const float*)g_ABC)[i];
        for (int i = t; i <= NB; i += THR) sbin[i] = g_bin[i];
        __syncthreads();
    }

    // ---- phase C: eval ----
    #pragma unroll
    for (int tile = 0; tile < IT; tile++) {
        long row = blockBase + (long)tile * THR + t;
        if (row >= N) break;
        int irow = (int)row;
        int run = max(rr[tile], seed);
        float xv = (run == irow) ? xr[tile] : __ldg(x + run);
        int bin = (int)((xv - XLO) * BINSCALE);
        bin = min(max(bin, 0), NB - 1);
        int lo = sbin[bin], hi = sbin[bin + 1];
        while (lo < hi) {
            int mid = (lo + hi) >> 1;
            if (scut[mid] < xv) lo = mid + 1; else hi = mid;
        }
        float2 ab = sAB[lo];
        float y = fmaf(ab.x, xv, ab.y);
        out[row] = (run == irow) ? y : y * __expf((float)(run - irow) * INV_TAU);
    }
}

#define LAUNCH_MAIN(ITV)                                                        \
    do {                                                                        \
        cudaFuncSetAttribute(k_main<ITV>,                                       \
            cudaFuncAttributeMaxDynamicSharedMemorySize, (int)smemB);           \
        k_main<ITV><<<grid1, THR, smemB>>>(x, out, N, out_size);                \
    } while (0)

extern "C" void kernel_launch(void* const* d_in, const int* in_sizes, int n_in,
                              void* d_out, int out_size) {
    const float* x  = (const float*)d_in[0];
    const float* W1 = (const float*)d_in[1];
    const float* b1 = (const float*)d_in[2];
    const float* W2 = (const float*)d_in[3];
    const float* b2 = (const float*)d_in[4];
    const float* W3 = (const float*)d_in[5];
    const float* b3 = (const float*)d_in[6];
    float* out = (float*)d_out;
    int N = in_sizes[0];

    k_sortbp<<<1, H>>>(W1, b1);
    k_build<<<NSEG, H>>>(W1, b1, W2, b2, W3, b3);
    k_compact<<<NSEG, H>>>();
    k_bins<<<(NB + 1 + 255) / 256, 256>>>();

    long total = N;
    int IT = (int)((total + (long)GRIDMAX * THR - 1) / ((long)GRIDMAX * THR));
    if (IT < 1) IT = 1;
    if (IT > 16) IT = 16;   // N here is fixed at 1M -> IT = 7
    int grid1 = (int)((total + (long)THR * IT - 1) / ((long)THR * IT));

    size_t smemB = (size_t)NCMAX * sizeof(float) + (size_t)NPMAX * sizeof(float2)
                 + (size_t)(NB + 1) * sizeof(unsigned short) + 16;

    switch (IT) {
        case 1:  LAUNCH_MAIN(1);  break;
        case 2:  LAUNCH_MAIN(2);  break;
        case 3:  LAUNCH_MAIN(3);  break;
        case 4:  LAUNCH_MAIN(4);  break;
        case 5:  LAUNCH_MAIN(5);  break;
        case 6:  LAUNCH_MAIN(6);  break;
        case 7:  LAUNCH_MAIN(7);  break;
        case 8:  LAUNCH_MAIN(8);  break;
        case 9:  LAUNCH_MAIN(9);  break;
        case 10: LAUNCH_MAIN(10); break;
        case 11: LAUNCH_MAIN(11); break;
        case 12: LAUNCH_MAIN(12); break;
        case 13: LAUNCH_MAIN(13); break;
        case 14: LAUNCH_MAIN(14); break;
        case 15: LAUNCH_MAIN(15); break;
        default: LAUNCH_MAIN(16); break;
    }
}